// round 1
// baseline (speedup 1.0000x reference)
#include <cuda_runtime.h>
#include <math.h>

#define B_ 512
#define T_ 512
#define I_ 256
#define H_ 250

// ---------------------------------------------------------------------------
// Kernel 1: xproj GEMM  out[m, n] = sum_k x[m,k] * Wx[n,k] + bh[n]
//   M = B*T = 262144, N = 250 (tiled to 4x64, predicated), K = 256
// ---------------------------------------------------------------------------
#define BM 128
#define BN 64
#define BK 32

__global__ __launch_bounds__(256) void xproj_kernel(
    const float* __restrict__ x, const float* __restrict__ Wx,
    const float* __restrict__ bh, float* __restrict__ out)
{
    __shared__ float As[BK][BM + 4];   // transposed: As[k][m]
    __shared__ float Bs[BK][BN + 4];   // transposed: Bs[k][n]

    const int m0  = blockIdx.x * BM;
    const int n0  = blockIdx.y * BN;
    const int tid = threadIdx.x;
    const int tn  = tid & 15;   // n-group (4 cols each)
    const int tm  = tid >> 4;   // m-group (8 rows each)

    float acc[8][4];
#pragma unroll
    for (int i = 0; i < 8; i++)
#pragma unroll
        for (int j = 0; j < 4; j++) acc[i][j] = 0.f;

    const int ar = tid >> 3;        // 0..31
    const int ac = (tid & 7) * 4;   // k offset (float4)

    for (int k0 = 0; k0 < I_; k0 += BK) {
        // load A tile 128x32 (4 float4 per thread), store transposed
#pragma unroll
        for (int p = 0; p < 4; p++) {
            int row = p * 32 + ar;
            float4 v = *(const float4*)(x + (size_t)(m0 + row) * I_ + k0 + ac);
            As[ac + 0][row] = v.x; As[ac + 1][row] = v.y;
            As[ac + 2][row] = v.z; As[ac + 3][row] = v.w;
        }
        // load B tile 64x32 (Wx rows, predicated n<250)
#pragma unroll
        for (int p = 0; p < 2; p++) {
            int row = p * 32 + ar;
            int n = n0 + row;
            float4 v = make_float4(0.f, 0.f, 0.f, 0.f);
            if (n < H_) v = *(const float4*)(Wx + (size_t)n * I_ + k0 + ac);
            Bs[ac + 0][row] = v.x; Bs[ac + 1][row] = v.y;
            Bs[ac + 2][row] = v.z; Bs[ac + 3][row] = v.w;
        }
        __syncthreads();

#pragma unroll
        for (int k = 0; k < BK; k++) {
            float4 a0 = *(const float4*)&As[k][tm * 8];
            float4 a1 = *(const float4*)&As[k][tm * 8 + 4];
            float4 bb = *(const float4*)&Bs[k][tn * 4];
            float a[8] = {a0.x, a0.y, a0.z, a0.w, a1.x, a1.y, a1.z, a1.w};
            float bv[4] = {bb.x, bb.y, bb.z, bb.w};
#pragma unroll
            for (int mm = 0; mm < 8; mm++)
#pragma unroll
                for (int nn = 0; nn < 4; nn++)
                    acc[mm][nn] = fmaf(a[mm], bv[nn], acc[mm][nn]);
        }
        __syncthreads();
    }

    // epilogue: out[m*250 + n] = acc + bh[n]   (n predicated)
#pragma unroll
    for (int nn = 0; nn < 4; nn++) {
        int n = n0 + tn * 4 + nn;
        if (n >= H_) continue;
        float bias = bh[n];
#pragma unroll
        for (int mm = 0; mm < 8; mm++) {
            int m = m0 + tm * 8 + mm;
            out[(size_t)m * H_ + n] = acc[mm][nn] + bias;
        }
    }
}

// ---------------------------------------------------------------------------
// Kernel 2: recurrence. Each CTA owns BTILE=4 batches, runs all T steps.
//   h_t[b,h] = tanh(out[b,t,h] + sum_k Wh[h,k] * h_{t-1}[b,k])
// Wh rows [0,HS) resident in smem; tail rows re-staged from L2 per k-tile.
// ---------------------------------------------------------------------------
#define HS    184          // smem-resident Wh rows
#define WSTR  260          // row stride for Wh_s (260 % 32 == 4 -> conflict-free)
#define TAILN 66           // 250 - 184 streamed rows
#define TSTR  127          // tail buffer stride (odd -> conflict-free)
#define TK    125          // k-tile for tail staging
#define BTILE 4
#define HPSTR 252

__global__ __launch_bounds__(256, 1) void rnn_rec_kernel(
    const float* __restrict__ h0, const float* __restrict__ Wh,
    float* __restrict__ out)
{
    extern __shared__ float smem[];
    float* Wh_s   = smem;                        // HS*WSTR
    float* tail_s = smem + HS * WSTR;            // TAILN*TSTR
    float* hp     = tail_s + TAILN * TSTR;       // BTILE*HPSTR

    const int tid = threadIdx.x;
    const int b0  = blockIdx.x * BTILE;
    const int h   = tid;
    const bool active = (h < H_);

    // one-time: load resident part of Wh into smem (padded)
    for (int idx = tid; idx < HS * H_; idx += 256) {
        int r = idx / H_;
        int c = idx - r * H_;
        Wh_s[r * WSTR + c] = Wh[idx];
    }
    // init hidden state from input h0
    for (int idx = tid; idx < BTILE * H_; idx += 256) {
        int b = idx / H_;
        int c = idx - b * H_;
        hp[b * HPSTR + c] = h0[(size_t)(b0 + b) * H_ + c];
    }
    const int  sr   = (tid < 125) ? 0 : 1;
    const int  sc   = tid - sr * 125;
    const bool sact = (tid < 250);
    __syncthreads();

    for (int t = 0; t < T_; t++) {
        // prefetch xproj values early (hide global latency under the dots)
        size_t o0 = ((size_t)(b0 + 0) * T_ + t) * H_ + h;
        size_t o1 = ((size_t)(b0 + 1) * T_ + t) * H_ + h;
        size_t o2 = ((size_t)(b0 + 2) * T_ + t) * H_ + h;
        size_t o3 = ((size_t)(b0 + 3) * T_ + t) * H_ + h;
        float xp0 = 0.f, xp1 = 0.f, xp2 = 0.f, xp3 = 0.f;
        if (active) { xp0 = out[o0]; xp1 = out[o1]; xp2 = out[o2]; xp3 = out[o3]; }

        float acc0 = 0.f, acc1 = 0.f, acc2 = 0.f, acc3 = 0.f;
#pragma unroll
        for (int kt = 0; kt < 2; kt++) {
            const int k0 = kt * TK;
            // stage tail Wh rows [HS,250) for k in [k0, k0+TK)  (coalesced)
            if (sact) {
#pragma unroll 4
                for (int rr = 0; rr < TAILN; rr += 2) {
                    int r = rr + sr;
                    tail_s[r * TSTR + sc] = Wh[(size_t)(HS + r) * H_ + k0 + sc];
                }
            }
            __syncthreads();
            if (active) {
                const float* wp = (h < HS) ? (Wh_s + h * WSTR + k0)
                                           : (tail_s + (h - HS) * TSTR);
                const float* p0 = hp + 0 * HPSTR + k0;
                const float* p1 = hp + 1 * HPSTR + k0;
                const float* p2 = hp + 2 * HPSTR + k0;
                const float* p3 = hp + 3 * HPSTR + k0;
#pragma unroll 5
                for (int kk = 0; kk < TK; kk++) {
                    float w = wp[kk];
                    acc0 = fmaf(w, p0[kk], acc0);
                    acc1 = fmaf(w, p1[kk], acc1);
                    acc2 = fmaf(w, p2[kk], acc2);
                    acc3 = fmaf(w, p3[kk], acc3);
                }
            }
            __syncthreads();
        }

        if (active) {
            float v0 = tanhf(xp0 + acc0);
            float v1 = tanhf(xp1 + acc1);
            float v2 = tanhf(xp2 + acc2);
            float v3 = tanhf(xp3 + acc3);
            out[o0] = v0; out[o1] = v1; out[o2] = v2; out[o3] = v3;
            // hp writes are ordered vs next step's reads by the staging barrier
            hp[0 * HPSTR + h] = v0;
            hp[1 * HPSTR + h] = v1;
            hp[2 * HPSTR + h] = v2;
            hp[3 * HPSTR + h] = v3;
        }
    }
}

// ---------------------------------------------------------------------------
extern "C" void kernel_launch(void* const* d_in, const int* in_sizes, int n_in,
                              void* d_out, int out_size)
{
    const float* x  = (const float*)d_in[0];
    const float* h0 = (const float*)d_in[1];
    const float* Wx = (const float*)d_in[2];
    const float* Wh = (const float*)d_in[3];
    const float* bh = (const float*)d_in[4];
    float* out = (float*)d_out;

    // 1) xproj + bias into d_out (scratch reuse, no allocation)
    dim3 g1((B_ * T_) / BM, (H_ + BN - 1) / BN);
    xproj_kernel<<<g1, 256>>>(x, Wx, bh, out);

    // 2) recurrence, in-place on d_out
    size_t smem2 = (size_t)(HS * WSTR + TAILN * TSTR + BTILE * HPSTR) * sizeof(float);
    cudaFuncSetAttribute(rnn_rec_kernel,
                         cudaFuncAttributeMaxDynamicSharedMemorySize, (int)smem2);
    rnn_rec_kernel<<<B_ / BTILE, 256, smem2>>>(h0, Wh, out);
}

// round 4
// speedup vs baseline: 2.2318x; 2.2318x over previous
#include <cuda_runtime.h>
#include <math.h>
#include <string.h>

#define B_ 512
#define T_ 512
#define I_ 256
#define H_ 250

// ---------------------------------------------------------------------------
// packed fp32x2 helpers (Blackwell dual fp32 pipe; ptxas never auto-emits)
// ---------------------------------------------------------------------------
__device__ __forceinline__ unsigned long long fma2(unsigned long long a,
                                                   unsigned long long b,
                                                   unsigned long long c) {
    unsigned long long d;
    asm("fma.rn.f32x2 %0, %1, %2, %3;" : "=l"(d) : "l"(a), "l"(b), "l"(c));
    return d;
}
__device__ __forceinline__ float2 u2f2(unsigned long long u) {
    float2 f; memcpy(&f, &u, 8); return f;
}
__device__ __forceinline__ unsigned long long f2u2(float x, float y) {
    unsigned long long u;
    asm("mov.b64 %0, {%1, %2};" : "=l"(u) : "f"(x), "f"(y));
    return u;
}

// ---------------------------------------------------------------------------
// Kernel 1: xproj GEMM  out[m, n] = sum_k x[m,k] * Wx[n,k] + bh[n]
//   M = B*T = 262144, N = 250 (4x64 tiles, predicated), K = 256
//   k-pair packed f32x2 accumulators; As/Bs row-major, stride 36 (9 float4,
//   odd in float4 granules -> conflict-free LDS.128)
// ---------------------------------------------------------------------------
#define BM 128
#define BN 64
#define BK 32
#define TSTRA 36

__global__ __launch_bounds__(256, 2) void xproj_kernel(
    const float* __restrict__ x, const float* __restrict__ Wx,
    const float* __restrict__ bh, float* __restrict__ out)
{
    __shared__ float As[BM][TSTRA];
    __shared__ float Bs[BN][TSTRA];

    const int m0  = blockIdx.x * BM;
    const int n0  = blockIdx.y * BN;
    const int tid = threadIdx.x;
    const int tn  = tid & 15;   // n-group (4 cols)
    const int tm  = tid >> 4;   // m-group (8 rows)

    unsigned long long acc[8][4];
#pragma unroll
    for (int i = 0; i < 8; i++)
#pragma unroll
        for (int j = 0; j < 4; j++) acc[i][j] = 0ull;

    const int ar = tid >> 3;        // 0..31
    const int ac = (tid & 7) * 4;   // k offset (float4)

    for (int k0 = 0; k0 < I_; k0 += BK) {
#pragma unroll
        for (int p = 0; p < 4; p++) {
            int row = p * 32 + ar;
            float4 v = *(const float4*)(x + (size_t)(m0 + row) * I_ + k0 + ac);
            *(float4*)&As[row][ac] = v;
        }
#pragma unroll
        for (int p = 0; p < 2; p++) {
            int row = p * 32 + ar;
            int n = n0 + row;
            float4 v = make_float4(0.f, 0.f, 0.f, 0.f);
            if (n < H_) v = *(const float4*)(Wx + (size_t)n * I_ + k0 + ac);
            *(float4*)&Bs[row][ac] = v;
        }
        __syncthreads();

#pragma unroll
        for (int j = 0; j < BK / 4; j++) {
            ulonglong2 b[4];
#pragma unroll
            for (int nn = 0; nn < 4; nn++)
                b[nn] = *(const ulonglong2*)&Bs[tn * 4 + nn][4 * j];
#pragma unroll
            for (int mm = 0; mm < 8; mm++) {
                ulonglong2 a = *(const ulonglong2*)&As[tm * 8 + mm][4 * j];
#pragma unroll
                for (int nn = 0; nn < 4; nn++) {
                    acc[mm][nn] = fma2(a.x, b[nn].x, acc[mm][nn]);
                    acc[mm][nn] = fma2(a.y, b[nn].y, acc[mm][nn]);
                }
            }
        }
        __syncthreads();
    }

#pragma unroll
    for (int nn = 0; nn < 4; nn++) {
        int n = n0 + tn * 4 + nn;
        if (n >= H_) continue;
        float bias = bh[n];
#pragma unroll
        for (int mm = 0; mm < 8; mm++) {
            int m = m0 + tm * 8 + mm;
            float2 f = u2f2(acc[mm][nn]);
            out[(size_t)m * H_ + n] = f.x + f.y + bias;
        }
    }
}

// ---------------------------------------------------------------------------
// Kernel 2: recurrence. CTA = 4 batches, thread = one hidden unit h.
//   h_t[b,h] = tanh(out[b,t,h] + sum_k Wh[h,k] * h_{t-1}[b,k])
// Wh k in [0,220) in smem (row stride 220 floats = 55 float4, odd ->
// conflict-free LDS.128); k in [220,250) in registers (15 f32x2 pairs).
// No per-step streaming, no divergent weight paths, 2 barriers per step.
// ---------------------------------------------------------------------------
#define RESK  220
#define WSTR  220
#define NREG  15           // 30 register weights = 15 f32x2 pairs per thread
#define HPSTR 252
#define BTILE 4

__global__ __launch_bounds__(256, 1) void rnn_rec_kernel(
    const float* __restrict__ h0, const float* __restrict__ Wh,
    float* __restrict__ out)
{
    extern __shared__ float smem[];
    float* Wh_s = smem;                     // 250 * 220 floats
    float* hp   = smem + H_ * WSTR;         // 4 * 252 floats

    const int tid = threadIdx.x;
    const int b0  = blockIdx.x * BTILE;
    const int h   = tid;
    const bool active = (h < H_);

    // one-time: load Wh k<220 into smem (coalesced in global)
    for (int idx = tid; idx < H_ * RESK; idx += 256) {
        int r = idx / RESK;
        int c = idx - r * RESK;
        Wh_s[r * WSTR + c] = Wh[(size_t)r * H_ + c];
    }
    // per-thread register weights: k in [220, 250)
    unsigned long long wreg[NREG];
    if (active) {
#pragma unroll
        for (int i = 0; i < NREG; i++) {
            float wa = Wh[(size_t)h * H_ + RESK + 2 * i];
            float wb = Wh[(size_t)h * H_ + RESK + 2 * i + 1];
            wreg[i] = f2u2(wa, wb);
        }
    }
    // hidden state hp[b][k], pad k in [250,252) zeroed
    for (int idx = tid; idx < BTILE * HPSTR; idx += 256) {
        int b = idx / HPSTR;
        int k = idx - b * HPSTR;
        hp[idx] = (k < H_) ? h0[(size_t)(b0 + b) * H_ + k] : 0.f;
    }
    __syncthreads();

    const float* wrow = Wh_s + h * WSTR;
    const float* hp0 = hp;
    const float* hp1 = hp + HPSTR;
    const float* hp2 = hp + 2 * HPSTR;
    const float* hp3 = hp + 3 * HPSTR;

    for (int t = 0; t < T_; t++) {
        size_t o0 = ((size_t)(b0 + 0) * T_ + t) * H_ + h;
        size_t o1 = ((size_t)(b0 + 1) * T_ + t) * H_ + h;
        size_t o2 = ((size_t)(b0 + 2) * T_ + t) * H_ + h;
        size_t o3 = ((size_t)(b0 + 3) * T_ + t) * H_ + h;
        float xp0 = 0.f, xp1 = 0.f, xp2 = 0.f, xp3 = 0.f;
        if (active) { xp0 = out[o0]; xp1 = out[o1]; xp2 = out[o2]; xp3 = out[o3]; }

        unsigned long long a0 = 0, a1 = 0, a2 = 0, a3 = 0;
        unsigned long long c0 = 0, c1 = 0, c2 = 0, c3 = 0;
        if (active) {
#pragma unroll 5
            for (int j = 0; j < RESK / 4; j++) {           // 55 blocks of 4 k
                ulonglong2 w  = *(const ulonglong2*)(wrow + 4 * j);
                ulonglong2 p0 = *(const ulonglong2*)(hp0 + 4 * j);
                ulonglong2 p1 = *(const ulonglong2*)(hp1 + 4 * j);
                ulonglong2 p2 = *(const ulonglong2*)(hp2 + 4 * j);
                ulonglong2 p3 = *(const ulonglong2*)(hp3 + 4 * j);
                a0 = fma2(w.x, p0.x, a0);  c0 = fma2(w.y, p0.y, c0);
                a1 = fma2(w.x, p1.x, a1);  c1 = fma2(w.y, p1.y, c1);
                a2 = fma2(w.x, p2.x, a2);  c2 = fma2(w.y, p2.y, c2);
                a3 = fma2(w.x, p3.x, a3);  c3 = fma2(w.y, p3.y, c3);
            }
#pragma unroll
            for (int i = 0; i < NREG; i++) {               // k = 220 .. 249
                const int k = RESK + 2 * i;
                unsigned long long w2 = wreg[i];
                a0 = fma2(w2, *(const unsigned long long*)(hp0 + k), a0);
                a1 = fma2(w2, *(const unsigned long long*)(hp1 + k), a1);
                a2 = fma2(w2, *(const unsigned long long*)(hp2 + k), a2);
                a3 = fma2(w2, *(const unsigned long long*)(hp3 + k), a3);
            }
        }
        __syncthreads();   // all hp reads complete

        if (active) {
            float2 f0a = u2f2(a0), f0c = u2f2(c0);
            float2 f1a = u2f2(a1), f1c = u2f2(c1);
            float2 f2a = u2f2(a2), f2c = u2f2(c2);
            float2 f3a = u2f2(a3), f3c = u2f2(c3);
            float v0 = tanhf(xp0 + (f0a.x + f0a.y) + (f0c.x + f0c.y));
            float v1 = tanhf(xp1 + (f1a.x + f1a.y) + (f1c.x + f1c.y));
            float v2 = tanhf(xp2 + (f2a.x + f2a.y) + (f2c.x + f2c.y));
            float v3 = tanhf(xp3 + (f3a.x + f3a.y) + (f3c.x + f3c.y));
            out[o0] = v0; out[o1] = v1; out[o2] = v2; out[o3] = v3;
            hp[0 * HPSTR + h] = v0;
            hp[1 * HPSTR + h] = v1;
            hp[2 * HPSTR + h] = v2;
            hp[3 * HPSTR + h] = v3;
        }
        __syncthreads();   // hp writes visible before next step's reads
    }
}

// ---------------------------------------------------------------------------
extern "C" void kernel_launch(void* const* d_in, const int* in_sizes, int n_in,
                              void* d_out, int out_size)
{
    const float* x  = (const float*)d_in[0];
    const float* h0 = (const float*)d_in[1];
    const float* Wx = (const float*)d_in[2];
    const float* Wh = (const float*)d_in[3];
    const float* bh = (const float*)d_in[4];
    float* out = (float*)d_out;

    // one-time, idempotent host-side attribute set (capture-legal; hoisted
    // out of steady-state anyway)
    static int attr_done = 0;
    size_t smem2 = (size_t)(H_ * WSTR + BTILE * HPSTR) * sizeof(float);
    if (!attr_done) {
        cudaFuncSetAttribute(rnn_rec_kernel,
                             cudaFuncAttributeMaxDynamicSharedMemorySize,
                             (int)smem2);
        attr_done = 1;
    }

    // 1) xproj + bias into d_out (scratch reuse, no allocation)
    dim3 g1((B_ * T_) / BM, (H_ + BN - 1) / BN);
    xproj_kernel<<<g1, 256>>>(x, Wx, bh, out);

    // 2) recurrence, in-place on d_out
    rnn_rec_kernel<<<B_ / BTILE, 256, smem2>>>(h0, Wh, out);
}